// round 15
// baseline (speedup 1.0000x reference)
#include <cuda_runtime.h>
#include <cuda_fp16.h>
#include <math.h>
#include <cstdint>

#define SEQ 2048
#define DIM 512

// ---------------------------------------------------------------------------
// Scratch (no cudaMalloc allowed)
// ---------------------------------------------------------------------------
__device__ __align__(16) __half g_xn_h  [SEQ * DIM];
__device__ __align__(16) __half g_wqkv_h[512 * 1536];
__device__ __align__(16) __half g_wout_h[512 * 512];
__device__ __align__(16) __half g_w1_h  [512 * 2048];
__device__ __align__(16) __half g_w2_h  [2048 * 512];
__device__ __align__(16) __half g_qkv_h [SEQ * 1536];
__device__ __align__(16) __half g_attn_h[SEQ * DIM];
__device__ __align__(16) float  g_out_f [SEQ * DIM];
__device__ __align__(16) __half g_out_h [SEQ * DIM];
__device__ __align__(16) __half g_f1_h  [SEQ * 2048];

// ---------------------------------------------------------------------------
// PTX helpers
// ---------------------------------------------------------------------------
__device__ __forceinline__ uint32_t smem_u32(const void* p) {
    uint32_t a;
    asm("{ .reg .u64 t; cvta.to.shared.u64 t, %1; cvt.u32.u64 %0, t; }"
        : "=r"(a) : "l"(p));
    return a;
}
#define CP_ASYNC16(dst, src) \
    asm volatile("cp.async.cg.shared.global [%0], [%1], 16;" :: "r"(dst), "l"(src))
#define CP_ASYNC16_Z(dst, src, sz) \
    asm volatile("cp.async.cg.shared.global [%0], [%1], 16, %2;" :: "r"(dst), "l"(src), "r"(sz))
#define CP_COMMIT()  asm volatile("cp.async.commit_group;" ::: "memory")
#define CP_WAIT1()   asm volatile("cp.async.wait_group 1;" ::: "memory")
#define CP_WAIT0()   asm volatile("cp.async.wait_group 0;" ::: "memory")

__device__ __forceinline__ void ldsm_x4(uint32_t& r0, uint32_t& r1,
                                        uint32_t& r2, uint32_t& r3, uint32_t a) {
    asm volatile("ldmatrix.sync.aligned.m8n8.x4.shared.b16 {%0,%1,%2,%3}, [%4];"
        : "=r"(r0), "=r"(r1), "=r"(r2), "=r"(r3) : "r"(a));
}
__device__ __forceinline__ void ldsm_x2(uint32_t& r0, uint32_t& r1, uint32_t a) {
    asm volatile("ldmatrix.sync.aligned.m8n8.x2.shared.b16 {%0,%1}, [%2];"
        : "=r"(r0), "=r"(r1) : "r"(a));
}
__device__ __forceinline__ void ldsm_x4_t(uint32_t& r0, uint32_t& r1,
                                          uint32_t& r2, uint32_t& r3, uint32_t a) {
    asm volatile("ldmatrix.sync.aligned.m8n8.x4.trans.shared.b16 {%0,%1,%2,%3}, [%4];"
        : "=r"(r0), "=r"(r1), "=r"(r2), "=r"(r3) : "r"(a));
}
__device__ __forceinline__ void mma16816(float* c, const uint32_t* a, const uint32_t* b) {
    asm volatile("mma.sync.aligned.m16n8k16.row.col.f32.f16.f16.f32 "
        "{%0,%1,%2,%3}, {%4,%5,%6,%7}, {%8,%9}, {%0,%1,%2,%3};"
        : "+f"(c[0]), "+f"(c[1]), "+f"(c[2]), "+f"(c[3])
        : "r"(a[0]), "r"(a[1]), "r"(a[2]), "r"(a[3]), "r"(b[0]), "r"(b[1]));
}

// ---------------------------------------------------------------------------
// Fused prep: blocks [0,3072) convert weights fp32->half;
//             blocks [3072,5120) LayerNorm row -> half.
// ---------------------------------------------------------------------------
__global__ void __launch_bounds__(256) prep_kernel(
    const float* __restrict__ wqkv, const float* __restrict__ wout,
    const float* __restrict__ w1,   const float* __restrict__ w2,
    __half* __restrict__ oqkv, __half* __restrict__ oout,
    __half* __restrict__ o1,   __half* __restrict__ o2,
    const float* __restrict__ x, const float* __restrict__ g,
    const float* __restrict__ bb, __half* __restrict__ y)
{
    int b = blockIdx.x;
    int tid = threadIdx.x;
    if (b < 3072) {
        const float* in; __half* out; int off;
        if      (b < 768)  { in = wqkv; out = oqkv; off = b; }
        else if (b < 1024) { in = wout; out = oout; off = b - 768; }
        else if (b < 2048) { in = w1;   out = o1;   off = b - 1024; }
        else               { in = w2;   out = o2;   off = b - 2048; }
        int i = off * 1024 + tid * 4;
        float4 v = *(const float4*)&in[i];
        __half2 h0 = __floats2half2_rn(v.x, v.y);
        __half2 h1 = __floats2half2_rn(v.z, v.w);
        uint2 u;
        u.x = *(uint32_t*)&h0;
        u.y = *(uint32_t*)&h1;
        *(uint2*)&out[i] = u;
        return;
    }
    int s = b - 3072;
    const float* xr = x + (size_t)s * DIM;
    float v0 = xr[tid], v1 = xr[tid + 256];
    float sum = v0 + v1, sq = v0 * v0 + v1 * v1;
    #pragma unroll
    for (int o = 16; o > 0; o >>= 1) {
        sum += __shfl_xor_sync(~0u, sum, o);
        sq  += __shfl_xor_sync(~0u, sq,  o);
    }
    __shared__ float ss[8], s2[8];
    int w = tid >> 5, l = tid & 31;
    if (l == 0) { ss[w] = sum; s2[w] = sq; }
    __syncthreads();
    float tot = 0.f, tot2 = 0.f;
    #pragma unroll
    for (int i = 0; i < 8; i++) { tot += ss[i]; tot2 += s2[i]; }
    float mu = tot * (1.0f / 512.0f);
    float inv = rsqrtf(tot2 * (1.0f / 512.0f) - mu * mu + 1e-5f);
    __half* yr = y + (size_t)s * DIM;
    yr[tid]       = __float2half((v0 - mu) * inv * g[tid]       + bb[tid]);
    yr[tid + 256] = __float2half((v1 - mu) * inv * g[tid + 256] + bb[tid + 256]);
}

// ---------------------------------------------------------------------------
// HMMA GEMM: 64x128 CTA tile, BK=64, 512 threads / 16 warps (4x4 grid,
// 16x32 per warp) -> 4 warps per SMSP for latency hiding.
// 4-stage cp.async pipeline, wait_group 1.
// EPI: 0 = +bias ; 1 = +bias +res ; 2 = gelu(+bias)
// ---------------------------------------------------------------------------
#define ASTR 72
#define BSTR 136
#define ASZ  (64 * ASTR * 2)          // 9216
#define BSZ  (64 * BSTR * 2)          // 17408
#define STG  (ASZ + BSZ)              // 26624
#define SMG  (4 * STG)                // 106496

template<int EPI, bool WF32, bool WH>
__global__ void __launch_bounds__(512) gemm_mma(
    const __half* __restrict__ A, const __half* __restrict__ B,
    const float* __restrict__ bias, const float* __restrict__ res,
    float* __restrict__ C, __half* __restrict__ Ch,
    int M, int N, int K)
{
    extern __shared__ char smem[];
    uint32_t sb = smem_u32(smem);

    int tid = threadIdx.x, wid = tid >> 5, lane = tid & 31;
    int bm = blockIdx.y * 64, bn = blockIdx.x * 128;
    int wm = wid >> 2, wn = wid & 3;     // 4x4 warp grid

    const int nK = K / 64;

    // A: 512 chunks (1/thread); B: 1024 chunks (2/thread)
    int ar_ = tid >> 3, ac_ = tid & 7;
    auto load_stage = [&](int kt, int s) {
        CP_ASYNC16(sb + s * STG + (ar_ * ASTR + ac_ * 8) * 2,
                   A + (size_t)(bm + ar_) * K + kt * 64 + ac_ * 8);
        #pragma unroll
        for (int i = 0; i < 2; i++) {
            int v = tid + i * 512;
            int k = v >> 4, c = v & 15;
            CP_ASYNC16(sb + s * STG + ASZ + (k * BSTR + c * 8) * 2,
                       B + (size_t)(kt * 64 + k) * N + bn + c * 8);
        }
    };

    int aru = lane & 15, acu = (lane >> 4) << 3;
    int bg = lane >> 3, brl = lane & 7;

    float acc[4][4] = {};

    load_stage(0, 0); CP_COMMIT();
    load_stage(1, 1); CP_COMMIT();
    load_stage(2, 2); CP_COMMIT();

    for (int kt = 0; kt < nK; kt++) {
        int s = kt & 3;
        CP_WAIT1();
        __syncthreads();
        if (kt + 3 < nK) load_stage(kt + 3, (kt + 3) & 3);
        CP_COMMIT();

        #pragma unroll
        for (int kk = 0; kk < 64; kk += 16) {
            uint32_t af[4], bf[4][2];
            ldsm_x4(af[0], af[1], af[2], af[3],
                    sb + s * STG + ((wm * 16 + aru) * ASTR + kk + acu) * 2);
            #pragma unroll
            for (int j2 = 0; j2 < 2; j2++) {
                uint32_t r0, r1, r2, r3;
                ldsm_x4_t(r0, r1, r2, r3,
                          sb + s * STG + ASZ +
                          ((kk + (bg & 1) * 8 + brl) * BSTR +
                           wn * 32 + j2 * 16 + (bg >> 1) * 8) * 2);
                bf[j2 * 2][0] = r0;     bf[j2 * 2][1] = r1;
                bf[j2 * 2 + 1][0] = r2; bf[j2 * 2 + 1][1] = r3;
            }
            #pragma unroll
            for (int j = 0; j < 4; j++)
                mma16816(acc[j], af, bf[j]);
        }
    }

    int tq = lane >> 2, tr = lane & 3;
    int row = bm + wm * 16 + tq;
    #pragma unroll
    for (int j = 0; j < 4; j++) {
        int col = bn + wn * 32 + j * 8 + tr * 2;
        float b0 = bias[col], b1 = bias[col + 1];
        float v0 = acc[j][0] + b0, v1 = acc[j][1] + b1;
        float v2 = acc[j][2] + b0, v3 = acc[j][3] + b1;
        size_t p0 = (size_t)row * N + col;
        size_t p1 = (size_t)(row + 8) * N + col;
        if (EPI == 1) {
            float2 r0 = *(const float2*)&res[p0];
            float2 r1 = *(const float2*)&res[p1];
            v0 += r0.x; v1 += r0.y; v2 += r1.x; v3 += r1.y;
        }
        if (EPI == 2) {
            v0 = 0.5f * v0 * (1.0f + erff(v0 * 0.70710678118654752f));
            v1 = 0.5f * v1 * (1.0f + erff(v1 * 0.70710678118654752f));
            v2 = 0.5f * v2 * (1.0f + erff(v2 * 0.70710678118654752f));
            v3 = 0.5f * v3 * (1.0f + erff(v3 * 0.70710678118654752f));
        }
        if (WF32) {
            *(float2*)&C[p0] = make_float2(v0, v1);
            *(float2*)&C[p1] = make_float2(v2, v3);
        }
        if (WH) {
            *(__half2*)&Ch[p0] = __floats2half2_rn(v0, v1);
            *(__half2*)&Ch[p1] = __floats2half2_rn(v2, v3);
        }
    }
}

// ---------------------------------------------------------------------------
// Tensor-core local attention (R14 version).
// ---------------------------------------------------------------------------
#define TS 64
#define WINP 192
#define QSTR 72
#define KSTR 72
#define VSTR 72
#define OPSTR 66

#define AOFF_Q 0
#define AOFF_K (AOFF_Q + 64 * QSTR * 2)
#define AOFF_V (AOFF_K + WINP * KSTR * 2)
#define AOFF_RM (AOFF_V + WINP * VSTR * 2)
#define AOFF_RS (AOFF_RM + 2 * 64 * 4)
#define AOFF_OP (AOFF_RS + 2 * 64 * 4)
#define SMA_TOTAL (AOFF_OP + 64 * OPSTR * 4)

__global__ void __launch_bounds__(256, 2) attn4_kernel(
    const __half* __restrict__ qkv, __half* __restrict__ attn_out)
{
    extern __shared__ char sm[];
    __half* qs = (__half*)(sm + AOFF_Q);
    __half* ks = (__half*)(sm + AOFF_K);
    __half* vs = (__half*)(sm + AOFF_V);
    float*  rm = (float*)(sm + AOFF_RM);
    float*  rs = (float*)(sm + AOFF_RS);
    float*  op = (float*)(sm + AOFF_OP);
    uint32_t qsb = smem_u32(qs), ksb = smem_u32(ks), vsb = smem_u32(vs);

    int h = blockIdx.y;
    int s0 = blockIdx.x * TS;
    int tid = threadIdx.x, wid = tid >> 5, lane = tid & 31;
    int wq = wid >> 1, wp = wid & 1;
    int g = lane >> 2, t4 = lane & 3;

    #pragma unroll
    for (int i = 0; i < 6; i++) {
        int v = tid + i * 256;
        int p = v >> 3, c = v & 7;
        int t = s0 - 64 + p;
        int valid = (t >= 0 && t < SEQ);
        int tc = valid ? t : 0;
        uint32_t sz = valid ? 16u : 0u;
        CP_ASYNC16_Z(ksb + (p * KSTR + c * 8) * 2,
                     qkv + (size_t)tc * 1536 + 512 + h * 64 + c * 8, sz);
        CP_ASYNC16_Z(vsb + (p * VSTR + c * 8) * 2,
                     qkv + (size_t)tc * 1536 + 1024 + h * 64 + c * 8, sz);
    }
    #pragma unroll
    for (int i = 0; i < 2; i++) {
        int v = tid + i * 256;
        int r = v >> 3, c = v & 7;
        CP_ASYNC16(qsb + (r * QSTR + c * 8) * 2,
                   qkv + (size_t)(s0 + r) * 1536 + h * 64 + c * 8);
    }
    CP_COMMIT();
    CP_WAIT0();
    __syncthreads();

    int aru = lane & 15, acu = (lane >> 4) << 3;
    int brr = lane & 7, bcc = ((lane >> 3) & 1) << 3;
    int bg = lane >> 3, brl = lane & 7;

    float acc_s[12][4] = {};
    #pragma unroll
    for (int kk = 0; kk < 64; kk += 16) {
        uint32_t af[4];
        ldsm_x4(af[0], af[1], af[2], af[3],
                qsb + ((wq * 16 + aru) * QSTR + kk + acu) * 2);
        #pragma unroll
        for (int j = 0; j < 12; j++) {
            uint32_t bf[2];
            ldsm_x2(bf[0], bf[1],
                    ksb + ((wp * 96 + j * 8 + brr) * KSTR + kk + bcc) * 2);
            mma16816(acc_s[j], af, bf);
        }
    }

    int r0 = wq * 16 + g, r1 = r0 + 8;
    float m0 = -1e30f, m1 = -1e30f;
    #pragma unroll
    for (int j = 0; j < 12; j++) {
        int c0 = wp * 96 + j * 8 + t4 * 2, c1 = c0 + 1;
        acc_s[j][0] = (c0 >= r0 && c0 <= r0 + 128) ? acc_s[j][0] * 0.125f : -1e30f;
        acc_s[j][1] = (c1 >= r0 && c1 <= r0 + 128) ? acc_s[j][1] * 0.125f : -1e30f;
        acc_s[j][2] = (c0 >= r1 && c0 <= r1 + 128) ? acc_s[j][2] * 0.125f : -1e30f;
        acc_s[j][3] = (c1 >= r1 && c1 <= r1 + 128) ? acc_s[j][3] * 0.125f : -1e30f;
        m0 = fmaxf(m0, fmaxf(acc_s[j][0], acc_s[j][1]));
        m1 = fmaxf(m1, fmaxf(acc_s[j][2], acc_s[j][3]));
    }
    #pragma unroll
    for (int o = 1; o <= 2; o <<= 1) {
        m0 = fmaxf(m0, __shfl_xor_sync(~0u, m0, o));
        m1 = fmaxf(m1, __shfl_xor_sync(~0u, m1, o));
    }
    if (t4 == 0) { rm[wp * 64 + r0] = m0; rm[wp * 64 + r1] = m1; }
    __syncthreads();
    m0 = fmaxf(m0, rm[(wp ^ 1) * 64 + r0]);
    m1 = fmaxf(m1, rm[(wp ^ 1) * 64 + r1]);

    float sm0 = 0.0f, sm1 = 0.0f;
    #pragma unroll
    for (int j = 0; j < 12; j++) {
        acc_s[j][0] = __expf(acc_s[j][0] - m0);
        acc_s[j][1] = __expf(acc_s[j][1] - m0);
        acc_s[j][2] = __expf(acc_s[j][2] - m1);
        acc_s[j][3] = __expf(acc_s[j][3] - m1);
        sm0 += acc_s[j][0] + acc_s[j][1];
        sm1 += acc_s[j][2] + acc_s[j][3];
    }
    #pragma unroll
    for (int o = 1; o <= 2; o <<= 1) {
        sm0 += __shfl_xor_sync(~0u, sm0, o);
        sm1 += __shfl_xor_sync(~0u, sm1, o);
    }
    if (t4 == 0) { rs[wp * 64 + r0] = sm0; rs[wp * 64 + r1] = sm1; }
    __syncthreads();
    float inv0 = 1.0f / (sm0 + rs[(wp ^ 1) * 64 + r0]);
    float inv1 = 1.0f / (sm1 + rs[(wp ^ 1) * 64 + r1]);

    float acc_o[8][4] = {};
    #pragma unroll
    for (int jt = 0; jt < 6; jt++) {
        uint32_t pf[4];
        __half2 p0 = __floats2half2_rn(acc_s[2*jt][0] * inv0, acc_s[2*jt][1] * inv0);
        __half2 p1 = __floats2half2_rn(acc_s[2*jt][2] * inv1, acc_s[2*jt][3] * inv1);
        __half2 p2 = __floats2half2_rn(acc_s[2*jt+1][0] * inv0, acc_s[2*jt+1][1] * inv0);
        __half2 p3 = __floats2half2_rn(acc_s[2*jt+1][2] * inv1, acc_s[2*jt+1][3] * inv1);
        pf[0] = *(uint32_t*)&p0; pf[1] = *(uint32_t*)&p1;
        pf[2] = *(uint32_t*)&p2; pf[3] = *(uint32_t*)&p3;

        int kpos = wp * 96 + jt * 16;
        #pragma unroll
        for (int nt = 0; nt < 4; nt++) {
            uint32_t v0, v1, v2, v3;
            ldsm_x4_t(v0, v1, v2, v3,
                      vsb + ((kpos + (bg & 1) * 8 + brl) * VSTR +
                             nt * 16 + (bg >> 1) * 8) * 2);
            uint32_t b0[2] = {v0, v1}, b1[2] = {v2, v3};
            mma16816(acc_o[nt * 2],     pf, b0);
            mma16816(acc_o[nt * 2 + 1], pf, b1);
        }
    }

    if (wp == 1) {
        #pragma unroll
        for (int j = 0; j < 8; j++) {
            int c = j * 8 + t4 * 2;
            *(float2*)&op[r0 * OPSTR + c] = make_float2(acc_o[j][0], acc_o[j][1]);
            *(float2*)&op[r1 * OPSTR + c] = make_float2(acc_o[j][2], acc_o[j][3]);
        }
    }
    __syncthreads();
    if (wp == 0) {
        #pragma unroll
        for (int j = 0; j < 8; j++) {
            int c = j * 8 + t4 * 2;
            float2 q0 = *(const float2*)&op[r0 * OPSTR + c];
            float2 q1 = *(const float2*)&op[r1 * OPSTR + c];
            *(__half2*)&attn_out[(size_t)(s0 + r0) * DIM + h * 64 + c] =
                __floats2half2_rn(acc_o[j][0] + q0.x, acc_o[j][1] + q0.y);
            *(__half2*)&attn_out[(size_t)(s0 + r1) * DIM + h * 64 + c] =
                __floats2half2_rn(acc_o[j][2] + q1.x, acc_o[j][3] + q1.y);
        }
    }
}

// ---------------------------------------------------------------------------
extern "C" void kernel_launch(void* const* d_in, const int* in_sizes, int n_in,
                              void* d_out, int out_size)
{
    const float* x     = (const float*)d_in[0];
    const float* w_qkv = (const float*)d_in[1];
    const float* b_qkv = (const float*)d_in[2];
    const float* w_out = (const float*)d_in[3];
    const float* b_out = (const float*)d_in[4];
    const float* ln_g  = (const float*)d_in[5];
    const float* ln_b  = (const float*)d_in[6];
    const float* w1    = (const float*)d_in[7];
    const float* b1    = (const float*)d_in[8];
    const float* w2    = (const float*)d_in[9];
    const float* b2    = (const float*)d_in[10];
    float* out = (float*)d_out;

    __half *xn, *wqkv, *wout, *w1h, *w2h, *qkv, *attn, *o_h, *f1;
    float *o_f;
    cudaGetSymbolAddress((void**)&xn,   g_xn_h);
    cudaGetSymbolAddress((void**)&wqkv, g_wqkv_h);
    cudaGetSymbolAddress((void**)&wout, g_wout_h);
    cudaGetSymbolAddress((void**)&w1h,  g_w1_h);
    cudaGetSymbolAddress((void**)&w2h,  g_w2_h);
    cudaGetSymbolAddress((void**)&qkv,  g_qkv_h);
    cudaGetSymbolAddress((void**)&attn, g_attn_h);
    cudaGetSymbolAddress((void**)&o_f,  g_out_f);
    cudaGetSymbolAddress((void**)&o_h,  g_out_h);
    cudaGetSymbolAddress((void**)&f1,   g_f1_h);

    cudaFuncSetAttribute(gemm_mma<0, false, true>,  cudaFuncAttributeMaxDynamicSharedMemorySize, SMG);
    cudaFuncSetAttribute(gemm_mma<2, false, true>,  cudaFuncAttributeMaxDynamicSharedMemorySize, SMG);
    cudaFuncSetAttribute(gemm_mma<1, true,  true>,  cudaFuncAttributeMaxDynamicSharedMemorySize, SMG);
    cudaFuncSetAttribute(gemm_mma<1, true,  false>, cudaFuncAttributeMaxDynamicSharedMemorySize, SMG);
    cudaFuncSetAttribute(attn4_kernel, cudaFuncAttributeMaxDynamicSharedMemorySize, SMA_TOTAL);

    // Fused weight-convert + LayerNorm
    prep_kernel<<<3072 + SEQ, 256>>>(w_qkv, w_out, w1, w2, wqkv, wout, w1h, w2h,
                                     x, ln_g, ln_b, xn);

    // QKV: 384 CTAs x 512 thr, nK=8
    gemm_mma<0, false, true><<<dim3(1536 / 128, SEQ / 64), 512, SMG>>>(
        xn, wqkv, b_qkv, nullptr, nullptr, qkv, SEQ, 1536, 512);
    // Local attention
    attn4_kernel<<<dim3(SEQ / TS, 8), 256, SMA_TOTAL>>>(qkv, attn);
    // Out-proj + residual(x): 128 CTAs x 512 thr, nK=8
    gemm_mma<1, true, true><<<dim3(512 / 128, SEQ / 64), 512, SMG>>>(
        attn, wout, b_out, x, o_f, o_h, SEQ, 512, 512);
    // FFN up + GELU: 512 CTAs x 512 thr, nK=8
    gemm_mma<2, false, true><<<dim3(2048 / 128, SEQ / 64), 512, SMG>>>(
        o_h, w1h, b1, nullptr, nullptr, f1, SEQ, 2048, 512);
    // FFN down + residual(o): 128 CTAs x 512 thr, nK=32
    gemm_mma<1, true, false><<<dim3(512 / 128, SEQ / 64), 512, SMG>>>(
        f1, w2h, b2, o_f, out, nullptr, SEQ, 512, 2048);
}

// round 16
// speedup vs baseline: 1.1506x; 1.1506x over previous
#include <cuda_runtime.h>
#include <cuda_fp16.h>
#include <math.h>
#include <cstdint>

#define SEQ 2048
#define DIM 512

// ---------------------------------------------------------------------------
// Scratch (no cudaMalloc allowed)
// ---------------------------------------------------------------------------
__device__ __align__(16) __half g_xn_h  [SEQ * DIM];
__device__ __align__(16) __half g_wqkv_h[512 * 1536];
__device__ __align__(16) __half g_wout_h[512 * 512];
__device__ __align__(16) __half g_w1_h  [512 * 2048];
__device__ __align__(16) __half g_w2_h  [2048 * 512];
__device__ __align__(16) __half g_qkv_h [SEQ * 1536];
__device__ __align__(16) __half g_attn_h[SEQ * DIM];
__device__ __align__(16) float  g_out_f [SEQ * DIM];
__device__ __align__(16) __half g_out_h [SEQ * DIM];
__device__ __align__(16) __half g_f1_h  [SEQ * 2048];

// ---------------------------------------------------------------------------
// PTX helpers
// ---------------------------------------------------------------------------
__device__ __forceinline__ uint32_t smem_u32(const void* p) {
    uint32_t a;
    asm("{ .reg .u64 t; cvta.to.shared.u64 t, %1; cvt.u32.u64 %0, t; }"
        : "=r"(a) : "l"(p));
    return a;
}
#define CP_ASYNC16(dst, src) \
    asm volatile("cp.async.cg.shared.global [%0], [%1], 16;" :: "r"(dst), "l"(src))
#define CP_ASYNC16_Z(dst, src, sz) \
    asm volatile("cp.async.cg.shared.global [%0], [%1], 16, %2;" :: "r"(dst), "l"(src), "r"(sz))
#define CP_COMMIT()  asm volatile("cp.async.commit_group;" ::: "memory")
#define CP_WAIT1()   asm volatile("cp.async.wait_group 1;" ::: "memory")
#define CP_WAIT0()   asm volatile("cp.async.wait_group 0;" ::: "memory")

__device__ __forceinline__ void ldsm_x4(uint32_t& r0, uint32_t& r1,
                                        uint32_t& r2, uint32_t& r3, uint32_t a) {
    asm volatile("ldmatrix.sync.aligned.m8n8.x4.shared.b16 {%0,%1,%2,%3}, [%4];"
        : "=r"(r0), "=r"(r1), "=r"(r2), "=r"(r3) : "r"(a));
}
__device__ __forceinline__ void ldsm_x2(uint32_t& r0, uint32_t& r1, uint32_t a) {
    asm volatile("ldmatrix.sync.aligned.m8n8.x2.shared.b16 {%0,%1}, [%2];"
        : "=r"(r0), "=r"(r1) : "r"(a));
}
__device__ __forceinline__ void ldsm_x4_t(uint32_t& r0, uint32_t& r1,
                                          uint32_t& r2, uint32_t& r3, uint32_t a) {
    asm volatile("ldmatrix.sync.aligned.m8n8.x4.trans.shared.b16 {%0,%1,%2,%3}, [%4];"
        : "=r"(r0), "=r"(r1), "=r"(r2), "=r"(r3) : "r"(a));
}
__device__ __forceinline__ void mma16816(float* c, const uint32_t* a, const uint32_t* b) {
    asm volatile("mma.sync.aligned.m16n8k16.row.col.f32.f16.f16.f32 "
        "{%0,%1,%2,%3}, {%4,%5,%6,%7}, {%8,%9}, {%0,%1,%2,%3};"
        : "+f"(c[0]), "+f"(c[1]), "+f"(c[2]), "+f"(c[3])
        : "r"(a[0]), "r"(a[1]), "r"(a[2]), "r"(a[3]), "r"(b[0]), "r"(b[1]));
}

// ---------------------------------------------------------------------------
// Fused prep: blocks [0,3072) convert weights fp32->half;
//             blocks [3072,5120) LayerNorm row -> half.
// ---------------------------------------------------------------------------
__global__ void __launch_bounds__(256) prep_kernel(
    const float* __restrict__ wqkv, const float* __restrict__ wout,
    const float* __restrict__ w1,   const float* __restrict__ w2,
    __half* __restrict__ oqkv, __half* __restrict__ oout,
    __half* __restrict__ o1,   __half* __restrict__ o2,
    const float* __restrict__ x, const float* __restrict__ g,
    const float* __restrict__ bb, __half* __restrict__ y)
{
    int b = blockIdx.x;
    int tid = threadIdx.x;
    if (b < 3072) {
        const float* in; __half* out; int off;
        if      (b < 768)  { in = wqkv; out = oqkv; off = b; }
        else if (b < 1024) { in = wout; out = oout; off = b - 768; }
        else if (b < 2048) { in = w1;   out = o1;   off = b - 1024; }
        else               { in = w2;   out = o2;   off = b - 2048; }
        int i = off * 1024 + tid * 4;
        float4 v = *(const float4*)&in[i];
        __half2 h0 = __floats2half2_rn(v.x, v.y);
        __half2 h1 = __floats2half2_rn(v.z, v.w);
        uint2 u;
        u.x = *(uint32_t*)&h0;
        u.y = *(uint32_t*)&h1;
        *(uint2*)&out[i] = u;
        return;
    }
    int s = b - 3072;
    const float* xr = x + (size_t)s * DIM;
    float v0 = xr[tid], v1 = xr[tid + 256];
    float sum = v0 + v1, sq = v0 * v0 + v1 * v1;
    #pragma unroll
    for (int o = 16; o > 0; o >>= 1) {
        sum += __shfl_xor_sync(~0u, sum, o);
        sq  += __shfl_xor_sync(~0u, sq,  o);
    }
    __shared__ float ss[8], s2[8];
    int w = tid >> 5, l = tid & 31;
    if (l == 0) { ss[w] = sum; s2[w] = sq; }
    __syncthreads();
    float tot = 0.f, tot2 = 0.f;
    #pragma unroll
    for (int i = 0; i < 8; i++) { tot += ss[i]; tot2 += s2[i]; }
    float mu = tot * (1.0f / 512.0f);
    float inv = rsqrtf(tot2 * (1.0f / 512.0f) - mu * mu + 1e-5f);
    __half* yr = y + (size_t)s * DIM;
    yr[tid]       = __float2half((v0 - mu) * inv * g[tid]       + bb[tid]);
    yr[tid + 256] = __float2half((v1 - mu) * inv * g[tid + 256] + bb[tid + 256]);
}

// ---------------------------------------------------------------------------
// HMMA GEMM (R12/R14 best-known config): 64x128 CTA tile, BK=64, 256 threads,
// 8 warps (2x4), warp 32x32, 4-stage cp.async, fragment double-buffering.
// EPI: 0 = +bias ; 1 = +bias +res ; 2 = gelu(+bias)
// ---------------------------------------------------------------------------
#define ASTR 72
#define BSTR 136
#define ASZ  (64 * ASTR * 2)
#define BSZ  (64 * BSTR * 2)
#define STG  (ASZ + BSZ)
#define SMG  (4 * STG)

template<int EPI, bool WF32, bool WH>
__global__ void __launch_bounds__(256) gemm_mma(
    const __half* __restrict__ A, const __half* __restrict__ B,
    const float* __restrict__ bias, const float* __restrict__ res,
    float* __restrict__ C, __half* __restrict__ Ch,
    int M, int N, int K)
{
    extern __shared__ char smem[];
    uint32_t sb = smem_u32(smem);

    int tid = threadIdx.x, wid = tid >> 5, lane = tid & 31;
    int bm = blockIdx.y * 64, bn = blockIdx.x * 128;
    int wm = wid >> 2, wn = wid & 3;

    const int nK = K / 64;

    auto load_stage = [&](int kt, int s) {
        #pragma unroll
        for (int i = 0; i < 2; i++) {
            int v = tid + i * 256;
            int r = v >> 3, c = v & 7;
            CP_ASYNC16(sb + s * STG + (r * ASTR + c * 8) * 2,
                       A + (size_t)(bm + r) * K + kt * 64 + c * 8);
        }
        #pragma unroll
        for (int i = 0; i < 4; i++) {
            int v = tid + i * 256;
            int k = v >> 4, c = v & 15;
            CP_ASYNC16(sb + s * STG + ASZ + (k * BSTR + c * 8) * 2,
                       B + (size_t)(kt * 64 + k) * N + bn + c * 8);
        }
    };

    int aru = lane & 15, acu = (lane >> 4) << 3;
    int bg = lane >> 3, brl = lane & 7;

    uint32_t af[2][2][4], bf[2][4][2];
    float acc[2][4][4] = {};

    auto ld_frags = [&](int s, int kk, int b) {
        #pragma unroll
        for (int i = 0; i < 2; i++)
            ldsm_x4(af[b][i][0], af[b][i][1], af[b][i][2], af[b][i][3],
                    sb + s * STG + ((wm * 32 + i * 16 + aru) * ASTR + kk + acu) * 2);
        #pragma unroll
        for (int j2 = 0; j2 < 2; j2++) {
            uint32_t r0, r1, r2, r3;
            ldsm_x4_t(r0, r1, r2, r3,
                      sb + s * STG + ASZ +
                      ((kk + (bg & 1) * 8 + brl) * BSTR +
                       wn * 32 + j2 * 16 + (bg >> 1) * 8) * 2);
            bf[b][j2 * 2][0] = r0;     bf[b][j2 * 2][1] = r1;
            bf[b][j2 * 2 + 1][0] = r2; bf[b][j2 * 2 + 1][1] = r3;
        }
    };
    auto do_mma = [&](int b) {
        #pragma unroll
        for (int i = 0; i < 2; i++)
            #pragma unroll
            for (int j = 0; j < 4; j++)
                mma16816(acc[i][j], af[b][i], bf[b][j]);
    };

    load_stage(0, 0); CP_COMMIT();
    load_stage(1, 1); CP_COMMIT();
    load_stage(2, 2); CP_COMMIT();

    for (int kt = 0; kt < nK; kt++) {
        int s = kt & 3;
        CP_WAIT1();
        __syncthreads();
        if (kt == 0) ld_frags(0, 0, 0);
        if (kt + 3 < nK) load_stage(kt + 3, (kt + 3) & 3);
        CP_COMMIT();
        ld_frags(s, 16, 1);  do_mma(0);
        ld_frags(s, 32, 0);  do_mma(1);
        ld_frags(s, 48, 1);  do_mma(0);
        if (kt + 1 < nK) ld_frags((kt + 1) & 3, 0, 0);
        do_mma(1);
    }

    int tq = lane >> 2, tr = lane & 3;
    #pragma unroll
    for (int i = 0; i < 2; i++) {
        int row = bm + wm * 32 + i * 16 + tq;
        #pragma unroll
        for (int j = 0; j < 4; j++) {
            int col = bn + wn * 32 + j * 8 + tr * 2;
            float b0 = bias[col], b1 = bias[col + 1];
            float v0 = acc[i][j][0] + b0, v1 = acc[i][j][1] + b1;
            float v2 = acc[i][j][2] + b0, v3 = acc[i][j][3] + b1;
            size_t p0 = (size_t)row * N + col;
            size_t p1 = (size_t)(row + 8) * N + col;
            if (EPI == 1) {
                float2 r0 = *(const float2*)&res[p0];
                float2 r1 = *(const float2*)&res[p1];
                v0 += r0.x; v1 += r0.y; v2 += r1.x; v3 += r1.y;
            }
            if (EPI == 2) {
                v0 = 0.5f * v0 * (1.0f + erff(v0 * 0.70710678118654752f));
                v1 = 0.5f * v1 * (1.0f + erff(v1 * 0.70710678118654752f));
                v2 = 0.5f * v2 * (1.0f + erff(v2 * 0.70710678118654752f));
                v3 = 0.5f * v3 * (1.0f + erff(v3 * 0.70710678118654752f));
            }
            if (WF32) {
                *(float2*)&C[p0] = make_float2(v0, v1);
                *(float2*)&C[p1] = make_float2(v2, v3);
            }
            if (WH) {
                *(__half2*)&Ch[p0] = __floats2half2_rn(v0, v1);
                *(__half2*)&Ch[p1] = __floats2half2_rn(v2, v3);
            }
        }
    }
}

// ---------------------------------------------------------------------------
// attn5: barrier-free tensor-core local attention.
// Block = 128 threads (4 warps); warp w owns q rows [16w,16w+16) x ALL 192
// positions -> softmax reductions are quad-shuffles only; no cross-warp SMEM.
// V staged in a separate cp.async group, overlapped with S + softmax.
// ---------------------------------------------------------------------------
#define TS 64
#define WINP 192
#define QSTR 72
#define KSTR 72
#define VSTR 72

#define AOFF_Q 0
#define AOFF_K (AOFF_Q + 64 * QSTR * 2)             // 9216
#define AOFF_V (AOFF_K + WINP * KSTR * 2)           // 36864
#define SMA_TOTAL (AOFF_V + WINP * VSTR * 2)        // 64512

__global__ void __launch_bounds__(128, 2) attn5_kernel(
    const __half* __restrict__ qkv, __half* __restrict__ attn_out)
{
    extern __shared__ char sm[];
    __half* qs = (__half*)(sm + AOFF_Q);
    __half* ks = (__half*)(sm + AOFF_K);
    __half* vs = (__half*)(sm + AOFF_V);
    uint32_t qsb = smem_u32(qs), ksb = smem_u32(ks), vsb = smem_u32(vs);

    int h = blockIdx.y;
    int s0 = blockIdx.x * TS;
    int tid = threadIdx.x, wid = tid >> 5, lane = tid & 31;
    int g = lane >> 2, t4 = lane & 3;

    // ---- group 0: stage K and Q ----
    #pragma unroll
    for (int i = 0; i < 12; i++) {
        int v = tid + i * 128;            // 0..1535
        int p = v >> 3, c = v & 7;
        int t = s0 - 64 + p;
        int valid = (t >= 0 && t < SEQ);
        int tc = valid ? t : 0;
        uint32_t sz = valid ? 16u : 0u;
        CP_ASYNC16_Z(ksb + (p * KSTR + c * 8) * 2,
                     qkv + (size_t)tc * 1536 + 512 + h * 64 + c * 8, sz);
    }
    #pragma unroll
    for (int i = 0; i < 4; i++) {
        int v = tid + i * 128;            // 0..511
        int r = v >> 3, c = v & 7;
        CP_ASYNC16(qsb + (r * QSTR + c * 8) * 2,
                   qkv + (size_t)(s0 + r) * 1536 + h * 64 + c * 8);
    }
    CP_COMMIT();
    // ---- group 1: stage V (overlaps S + softmax) ----
    #pragma unroll
    for (int i = 0; i < 12; i++) {
        int v = tid + i * 128;
        int p = v >> 3, c = v & 7;
        int t = s0 - 64 + p;
        int valid = (t >= 0 && t < SEQ);
        int tc = valid ? t : 0;
        uint32_t sz = valid ? 16u : 0u;
        CP_ASYNC16_Z(vsb + (p * VSTR + c * 8) * 2,
                     qkv + (size_t)tc * 1536 + 1024 + h * 64 + c * 8, sz);
    }
    CP_COMMIT();

    CP_WAIT1();            // K + Q complete
    __syncthreads();

    int aru = lane & 15, acu = (lane >> 4) << 3;
    int brr = lane & 7, bcc = ((lane >> 3) & 1) << 3;
    int bg = lane >> 3, brl = lane & 7;

    // ---- S = Q @ K^T : 16 q-rows x 192 positions per warp ----
    float acc_s[24][4] = {};
    #pragma unroll
    for (int kk = 0; kk < 64; kk += 16) {
        uint32_t af[4];
        ldsm_x4(af[0], af[1], af[2], af[3],
                qsb + ((wid * 16 + aru) * QSTR + kk + acu) * 2);
        #pragma unroll
        for (int j = 0; j < 24; j++) {
            uint32_t bf[2];
            ldsm_x2(bf[0], bf[1],
                    ksb + ((j * 8 + brr) * KSTR + kk + bcc) * 2);
            mma16816(acc_s[j], af, bf);
        }
    }

    // ---- scale + window mask + softmax (quad shuffles only) ----
    int r0 = wid * 16 + g, r1 = r0 + 8;
    float m0 = -1e30f, m1 = -1e30f;
    #pragma unroll
    for (int j = 0; j < 24; j++) {
        int c0 = j * 8 + t4 * 2, c1 = c0 + 1;
        acc_s[j][0] = (c0 >= r0 && c0 <= r0 + 128) ? acc_s[j][0] * 0.125f : -1e30f;
        acc_s[j][1] = (c1 >= r0 && c1 <= r0 + 128) ? acc_s[j][1] * 0.125f : -1e30f;
        acc_s[j][2] = (c0 >= r1 && c0 <= r1 + 128) ? acc_s[j][2] * 0.125f : -1e30f;
        acc_s[j][3] = (c1 >= r1 && c1 <= r1 + 128) ? acc_s[j][3] * 0.125f : -1e30f;
        m0 = fmaxf(m0, fmaxf(acc_s[j][0], acc_s[j][1]));
        m1 = fmaxf(m1, fmaxf(acc_s[j][2], acc_s[j][3]));
    }
    #pragma unroll
    for (int o = 1; o <= 2; o <<= 1) {
        m0 = fmaxf(m0, __shfl_xor_sync(~0u, m0, o));
        m1 = fmaxf(m1, __shfl_xor_sync(~0u, m1, o));
    }
    float sm0 = 0.0f, sm1 = 0.0f;
    #pragma unroll
    for (int j = 0; j < 24; j++) {
        acc_s[j][0] = __expf(acc_s[j][0] - m0);
        acc_s[j][1] = __expf(acc_s[j][1] - m0);
        acc_s[j][2] = __expf(acc_s[j][2] - m1);
        acc_s[j][3] = __expf(acc_s[j][3] - m1);
        sm0 += acc_s[j][0] + acc_s[j][1];
        sm1 += acc_s[j][2] + acc_s[j][3];
    }
    #pragma unroll
    for (int o = 1; o <= 2; o <<= 1) {
        sm0 += __shfl_xor_sync(~0u, sm0, o);
        sm1 += __shfl_xor_sync(~0u, sm1, o);
    }
    float inv0 = 1.0f / sm0, inv1 = 1.0f / sm1;

    // ---- wait for V, then O = P @ V (full 64 dims per warp) ----
    CP_WAIT0();
    __syncthreads();

    float acc_o[8][4] = {};
    #pragma unroll
    for (int jt = 0; jt < 12; jt++) {
        uint32_t pf[4];
        __half2 p0 = __floats2half2_rn(acc_s[2*jt][0] * inv0, acc_s[2*jt][1] * inv0);
        __half2 p1 = __floats2half2_rn(acc_s[2*jt][2] * inv1, acc_s[2*jt][3] * inv1);
        __half2 p2 = __floats2half2_rn(acc_s[2*jt+1][0] * inv0, acc_s[2*jt+1][1] * inv0);
        __half2 p3 = __floats2half2_rn(acc_s[2*jt+1][2] * inv1, acc_s[2*jt+1][3] * inv1);
        pf[0] = *(uint32_t*)&p0; pf[1] = *(uint32_t*)&p1;
        pf[2] = *(uint32_t*)&p2; pf[3] = *(uint32_t*)&p3;

        int kpos = jt * 16;
        #pragma unroll
        for (int nt = 0; nt < 4; nt++) {
            uint32_t v0, v1, v2, v3;
            ldsm_x4_t(v0, v1, v2, v3,
                      vsb + ((kpos + (bg & 1) * 8 + brl) * VSTR +
                             nt * 16 + (bg >> 1) * 8) * 2);
            uint32_t b0[2] = {v0, v1}, b1[2] = {v2, v3};
            mma16816(acc_o[nt * 2],     pf, b0);
            mma16816(acc_o[nt * 2 + 1], pf, b1);
        }
    }

    #pragma unroll
    for (int j = 0; j < 8; j++) {
        int c = h * 64 + j * 8 + t4 * 2;
        *(__half2*)&attn_out[(size_t)(s0 + r0) * DIM + c] =
            __floats2half2_rn(acc_o[j][0], acc_o[j][1]);
        *(__half2*)&attn_out[(size_t)(s0 + r1) * DIM + c] =
            __floats2half2_rn(acc_o[j][2], acc_o[j][3]);
    }
}

// ---------------------------------------------------------------------------
extern "C" void kernel_launch(void* const* d_in, const int* in_sizes, int n_in,
                              void* d_out, int out_size)
{
    const float* x     = (const float*)d_in[0];
    const float* w_qkv = (const float*)d_in[1];
    const float* b_qkv = (const float*)d_in[2];
    const float* w_out = (const float*)d_in[3];
    const float* b_out = (const float*)d_in[4];
    const float* ln_g  = (const float*)d_in[5];
    const float* ln_b  = (const float*)d_in[6];
    const float* w1    = (const float*)d_in[7];
    const float* b1    = (const float*)d_in[8];
    const float* w2    = (const float*)d_in[9];
    const float* b2    = (const float*)d_in[10];
    float* out = (float*)d_out;

    __half *xn, *wqkv, *wout, *w1h, *w2h, *qkv, *attn, *o_h, *f1;
    float *o_f;
    cudaGetSymbolAddress((void**)&xn,   g_xn_h);
    cudaGetSymbolAddress((void**)&wqkv, g_wqkv_h);
    cudaGetSymbolAddress((void**)&wout, g_wout_h);
    cudaGetSymbolAddress((void**)&w1h,  g_w1_h);
    cudaGetSymbolAddress((void**)&w2h,  g_w2_h);
    cudaGetSymbolAddress((void**)&qkv,  g_qkv_h);
    cudaGetSymbolAddress((void**)&attn, g_attn_h);
    cudaGetSymbolAddress((void**)&o_f,  g_out_f);
    cudaGetSymbolAddress((void**)&o_h,  g_out_h);
    cudaGetSymbolAddress((void**)&f1,   g_f1_h);

    cudaFuncSetAttribute(gemm_mma<0, false, true>,  cudaFuncAttributeMaxDynamicSharedMemorySize, SMG);
    cudaFuncSetAttribute(gemm_mma<2, false, true>,  cudaFuncAttributeMaxDynamicSharedMemorySize, SMG);
    cudaFuncSetAttribute(gemm_mma<1, true,  true>,  cudaFuncAttributeMaxDynamicSharedMemorySize, SMG);
    cudaFuncSetAttribute(gemm_mma<1, true,  false>, cudaFuncAttributeMaxDynamicSharedMemorySize, SMG);
    cudaFuncSetAttribute(attn5_kernel, cudaFuncAttributeMaxDynamicSharedMemorySize, SMA_TOTAL);

    // Fused weight-convert + LayerNorm
    prep_kernel<<<3072 + SEQ, 256>>>(w_qkv, w_out, w1, w2, wqkv, wout, w1h, w2h,
                                     x, ln_g, ln_b, xn);

    // QKV: 384 CTAs, nK=8
    gemm_mma<0, false, true><<<dim3(1536 / 128, SEQ / 64), 256, SMG>>>(
        xn, wqkv, b_qkv, nullptr, nullptr, qkv, SEQ, 1536, 512);
    // Local attention: 256 blocks x 128 thr, barrier-free softmax
    attn5_kernel<<<dim3(SEQ / TS, 8), 128, SMA_TOTAL>>>(qkv, attn);
    // Out-proj + residual(x): 128 CTAs, nK=8
    gemm_mma<1, true, true><<<dim3(512 / 128, SEQ / 64), 256, SMG>>>(
        attn, wout, b_out, x, o_f, o_h, SEQ, 512, 512);
    // FFN up + GELU: 512 CTAs, nK=8
    gemm_mma<2, false, true><<<dim3(2048 / 128, SEQ / 64), 256, SMG>>>(
        o_h, w1h, b1, nullptr, nullptr, f1, SEQ, 2048, 512);
    // FFN down + residual(o): 128 CTAs, nK=32
    gemm_mma<1, true, false><<<dim3(512 / 128, SEQ / 64), 256, SMG>>>(
        f1, w2h, b2, o_f, out, nullptr, SEQ, 512, 2048);
}